// round 17
// baseline (speedup 1.0000x reference)
#include <cuda_runtime.h>
#include <cuda_bf16.h>

// NDFT type-2, conjugate-pair symmetry over k1 (f_hat real):
//   pair +-t: f[t]e^{-ip} + f[-t]e^{+ip} = fs*cos(p) - i*fd*sin(p)
//   t=0: fs=f (fd killed by sin(0)=0 exact); t=32 (k1=-32): fs=f, fd=-f;
//   t=33: zero pad. Radix on k2: k2 = 16a + c - 32.
// Block: 256 thr = 8 warps = (a, t-half h), 32 points.
// Lane = (p in [0,16), c-half ch); each lane owns points p and p+16.
// MUFU-minimized: cos/sin tables built by per-segment anchor (__sincosf) +
// complex-multiply recurrence (FMA pipe); step twiddle computed by one leader
// lane per 8-thread group and shfl'd. Tail twiddles (C_a * w2^c) folded into
// w2tab[c][p] = cis(-2*pi*x2[p]*(c-32)) -> tail has ZERO MUFU.
// Hot loop: (P,Q) += (fs,fd)*(cos,sin) as packed fma.rn.f32x2, cs via LDS.64.

#define B_DIM 2
#define M_DIM 8192
#define N1 64
#define N2 64
#define K_TOT (N1 * N2)
#define TPB 256
#define PTS 32
#define BLOCKS_PER_B (M_DIM / PTS)           // 256
#define TROWS 34                             // t = 0..32 + zero pad
#define ROWS_PW 17

#define TWO_PI_F 6.28318530717959f

typedef unsigned long long ull;

#define FMA2(d, a, b, c) \
    asm("fma.rn.f32x2 %0, %1, %2, %3;" : "=l"(d) : "l"(a), "l"(b), "l"(c))
#define UNPACK2(lo, hi, s) do { unsigned int _l, _h; \
    asm("mov.b64 {%0, %1}, %2;" : "=r"(_l), "=r"(_h) : "l"(s)); \
    (lo) = __uint_as_float(_l); (hi) = __uint_as_float(_h); } while (0)

__global__ __launch_bounds__(TPB, 4) void ndft_kernel(
    const float* __restrict__ x,      // [B, M, 2]
    const float* __restrict__ f_hat,  // [B, 64, 64]
    float* __restrict__ out,
    const int real_only)
{
    __shared__ __align__(16) float sfd[TROWS * 128];    // (fs,fd) interleaved
    __shared__ __align__(8) float2 cstab[TROWS * PTS];  // cis(2pi x1 t)[t][p]
    __shared__ __align__(8) float2 w2tab[N2 * PTS];     // cis(-2pi x2 (c-32))[c][p]
    __shared__ float2 sy[16][PTS];                      // partials per point

    const int b    = blockIdx.x / BLOCKS_PER_B;
    const int mblk = blockIdx.x % BLOCKS_PER_B;
    const int tid  = threadIdx.x;
    const int w    = tid >> 5;
    const int lane = tid & 31;
    const int a    = w & 3;                  // k2 radix digit
    const int h    = w >> 2;                 // t-half
    const int p    = lane & 15;              // first point; second = p + 16
    const int ch   = lane >> 4;              // c-half: c_loc = 8*ch + j
    const int mbase = b * M_DIM + mblk * PTS;

    // ---- build fs/fd interleaved: sfd[t*128 + c64*2] = (fs, fd) ----
    {
        const float* fb = f_hat + b * K_TOT;
        for (int idx = tid; idx < TROWS * 16; idx += TPB) {
            const int t = idx >> 4;
            const int g = idx & 15;
            float4 fp = make_float4(0.f, 0.f, 0.f, 0.f);
            float4 fm = make_float4(0.f, 0.f, 0.f, 0.f);
            if (t >= 1 && t <= 31)
                fp = *reinterpret_cast<const float4*>(fb + (32 + t) * N2 + g * 4);
            if (t <= 32)
                fm = *reinterpret_cast<const float4*>(fb + (32 - t) * N2 + g * 4);
            float4* dst = reinterpret_cast<float4*>(sfd + t * 128 + g * 8);
            dst[0] = make_float4(fp.x + fm.x, fp.x - fm.x, fp.y + fm.y, fp.y - fm.y);
            dst[1] = make_float4(fp.z + fm.z, fp.z - fm.z, fp.w + fm.w, fp.w - fm.w);
        }
    }

    // ---- build twiddle tables by anchor + recurrence (MUFU-light) ----
    {
        const int bp = tid >> 3;             // point 0..31
        const int bs = tid & 7;              // segment 0..7
        const float2 xv = reinterpret_cast<const float2*>(x)[mbase + bp];
        const float x1p = xv.x, x2p = xv.y;

        // leader lane of each 8-group computes the two step twiddles
        float wr = 0.f, wi = 0.f, vr = 0.f, vi = 0.f;
        if (bs == 0) {
            __sincosf(TWO_PI_F * x1p, &wi, &wr);     // cis(+2pi x1)
            __sincosf(-TWO_PI_F * x2p, &vi, &vr);    // cis(-2pi x2)
        }
        const int src = lane & ~7;
        wr = __shfl_sync(0xffffffffu, wr, src);
        wi = __shfl_sync(0xffffffffu, wi, src);
        vr = __shfl_sync(0xffffffffu, vr, src);
        vi = __shfl_sync(0xffffffffu, vi, src);

        // cstab: t = 4*bs .. (bs==7 ? 33 : 4*bs+3); cis(2pi x1 t)
        {
            float cr, ci;
            __sincosf(TWO_PI_F * x1p * (float)(4 * bs), &ci, &cr);
            const int tend = (bs == 7) ? TROWS : 4 * bs + 4;
            for (int t = 4 * bs; t < tend; ++t) {
                cstab[t * PTS + bp] = make_float2(cr, ci);
                const float nr = cr * wr - ci * wi;
                ci = cr * wi + ci * wr;
                cr = nr;
            }
        }
        // w2tab: c = 8*bs .. 8*bs+7; cis(-2pi x2 (c-32))
        {
            float cr, ci;
            __sincosf(-TWO_PI_F * x2p * (float)(8 * bs - 32), &ci, &cr);
            #pragma unroll
            for (int j = 0; j < 8; ++j) {
                w2tab[(8 * bs + j) * PTS + bp] = make_float2(cr, ci);
                const float nr = cr * vr - ci * vi;
                ci = cr * vi + ci * vr;
                cr = nr;
            }
        }
    }
    __syncthreads();

    // packed accumulators: accK[j] = (P, Q) for point K, local c = 8*ch + j
    ull acc0[8], acc1[8];
    #pragma unroll
    for (int j = 0; j < 8; ++j) { acc0[j] = 0ull; acc1[j] = 0ull; }

    // this lane's f slice: 4 x 16B per row, at a*128B + ch*64B
    const ulonglong2* fsd = reinterpret_cast<const ulonglong2*>(
        sfd + (h * ROWS_PW) * 128 + a * 32 + ch * 16);
    // this lane's cs pointers (2 points), stride 32 float2 per row
    const ull* cs0p = reinterpret_cast<const ull*>(cstab + (h * ROWS_PW) * PTS + p);
    const ull* cs1p = cs0p + 16;

    #pragma unroll
    for (int t = 0; t < ROWS_PW; ++t) {
        const ull cs0 = cs0p[t * PTS];   // (cos,sin) point p   — LDS.64
        const ull cs1 = cs1p[t * PTS];   // (cos,sin) point p+16

        const ulonglong2 v0 = fsd[0];    // (fs,fd) pairs c = 8ch+0..3
        const ulonglong2 v1 = fsd[1];
        const ulonglong2 v2 = fsd[2];    // c = 8ch+4..7
        const ulonglong2 v3 = fsd[3];

        FMA2(acc0[0], v0.x, cs0, acc0[0]);
        FMA2(acc1[0], v0.x, cs1, acc1[0]);
        FMA2(acc0[1], v0.y, cs0, acc0[1]);
        FMA2(acc1[1], v0.y, cs1, acc1[1]);
        FMA2(acc0[2], v1.x, cs0, acc0[2]);
        FMA2(acc1[2], v1.x, cs1, acc1[2]);
        FMA2(acc0[3], v1.y, cs0, acc0[3]);
        FMA2(acc1[3], v1.y, cs1, acc1[3]);
        FMA2(acc0[4], v2.x, cs0, acc0[4]);
        FMA2(acc1[4], v2.x, cs1, acc1[4]);
        FMA2(acc0[5], v2.y, cs0, acc0[5]);
        FMA2(acc1[5], v2.y, cs1, acc1[5]);
        FMA2(acc0[6], v3.x, cs0, acc0[6]);
        FMA2(acc1[6], v3.x, cs1, acc1[6]);
        FMA2(acc0[7], v3.y, cs0, acc0[7]);
        FMA2(acc1[7], v3.y, cs1, acc1[7]);

        fsd += 32;                       // next t row (128 floats)
    }

    // ---- tail (no MUFU): y_partial = sum_j w2tab[16a+8ch+j] * (P_j - i Q_j)
    #pragma unroll
    for (int k = 0; k < 2; ++k) {
        const ull* acc = k ? acc1 : acc0;
        const int pp = p + 16 * k;
        const float2* wrow = w2tab + (16 * a + 8 * ch) * PTS + pp;

        float Tr = 0.0f, Ti = 0.0f;
        #pragma unroll
        for (int j = 0; j < 8; ++j) {
            const float2 wv = wrow[j * PTS];   // LDS.64
            float P, Q;
            UNPACK2(P, Q, acc[j]);
            Tr += wv.x * P + wv.y * Q;
            Ti += wv.y * P - wv.x * Q;
        }
        sy[w * 2 + ch][pp] = make_float2(Tr, Ti);
    }
    __syncthreads();

    // ---- reduction: 16 partials per point ----
    if (tid < PTS) {
        float2 s = sy[0][tid];
        #pragma unroll
        for (int q = 1; q < 16; ++q) {
            s.x += sy[q][tid].x;
            s.y += sy[q][tid].y;
        }
        const int mo = mbase + tid;
        if (real_only) {
            out[mo] = s.x;
        } else {
            reinterpret_cast<float2*>(out)[mo] = s;
        }
    }
}

extern "C" void kernel_launch(void* const* d_in, const int* in_sizes, int n_in,
                              void* d_out, int out_size) {
    // Select inputs by element count (metadata order may differ):
    //   x: 2*8192*2 = 32768, f_hat: 2*64*64 = 8192
    const float* x;
    const float* f_hat;
    if (in_sizes[0] == B_DIM * M_DIM * 2) {
        x = (const float*)d_in[0];
        f_hat = (const float*)d_in[1];
    } else {
        x = (const float*)d_in[1];
        f_hat = (const float*)d_in[0];
    }

    float* out = (float*)d_out;
    const int real_only = (out_size == B_DIM * M_DIM) ? 1 : 0;

    ndft_kernel<<<B_DIM * BLOCKS_PER_B, TPB>>>(x, f_hat, out, real_only);
}